// round 11
// baseline (speedup 1.0000x reference)
#include <cuda_runtime.h>

#define G       37
#define NPATCH  (G * G)          // 1369
#define D       768
#define NCUE    5
#define STOK    (NCUE + NPATCH)  // 1374
#define BATCH   128
#define EPSN    1e-12f

#define TPB     128              // thread owns rows 2t, 2t+1
#define PTILE   256              // rows per block
#define NTILE   6                // ceil(1369/256)
#define DC      16               // dims per stage (64B per row)
#define NS      (D / DC)         // 48 stages
#define NBUF    3
#define STAGE_B (PTILE * DC * 4)             // 16384 B per buffer
#define DSM_B   (NBUF * STAGE_B + NCUE * D * 4)  // 49152 + 15360 = 64512

// packed argmax scratch: high 32 = orderable sim key, low 32 = ~idx (lowest idx
// wins ties). Zero-init at module load; gather_kernel resets after reading so
// every graph replay is deterministic.
__device__ unsigned long long g_best[BATCH * NCUE];

__device__ __forceinline__ unsigned f2key(float f) {
    unsigned u = __float_as_uint(f);
    return (u & 0x80000000u) ? ~u : (u | 0x80000000u);
}
__device__ __forceinline__ void fma2(unsigned long long& d, unsigned long long a,
                                     unsigned long long b) {
    asm volatile("fma.rn.f32x2 %0, %1, %2, %0;" : "+l"(d) : "l"(a), "l"(b));
}
__device__ __forceinline__ void lds_v2u64(unsigned long long& lo, unsigned long long& hi,
                                          unsigned addr) {
    asm volatile("ld.shared.v2.u64 {%0, %1}, [%2];" : "=l"(lo), "=l"(hi) : "r"(addr));
}
__device__ __forceinline__ void cp16(unsigned dst, const void* src) {
    asm volatile("cp.async.cg.shared.global [%0], [%1], 16;" :: "r"(dst), "l"(src)
                 : "memory");
}

// ---------------------------------------------------------------------------
// Kernel 1: per-(batch,cue) argmax over patch dot-products.
// P=2 adjacent rows per thread: each broadcast cue LDS.128 feeds 2 rows, so
// per stage a thread does 8 patch + 20 cue LDS (vs 48 in R9) -> chip LDS
// crossbar time ~60us, below the DRAM floor. Smem block of pair P is 128B
// with unit swizzle u^(P&7): reads give distinct units per 8-lane phase and
// cp.async writes are contiguous 128B per 8-lane group -> conflict-free.
// 3-buffer ring (dyn smem 63KB, 3 blocks/SM, 12 warps): ~120KB/SM in flight.
// ---------------------------------------------------------------------------
__global__ __launch_bounds__(TPB, 3) void argmax_kernel(const float* __restrict__ tokens) {
    extern __shared__ char dsm[];                 // [3 x 16KB stages][15KB cues]
    float* cue_sm = (float*)(dsm + NBUF * STAGE_B);
    __shared__ unsigned long long warp_best[TPB / 32][NCUE];

    const int b    = blockIdx.y;
    const int t    = threadIdx.x;
    const int lane = t & 31;
    const int warp = t >> 5;
    const float* base  = tokens + (size_t)b * STOK * D;
    const float* patch = base + NCUE * D;
    const unsigned sb0 = (unsigned)__cvta_generic_to_shared(dsm);
    const int p0 = blockIdx.x * PTILE;

    // Copy descriptors: instr q (0..7): lane l serves pair P = 32w+4q+(l>>3),
    // logical 16B unit u=l&7 (u<4: even row, u>=4: odd row). smem dst is the
    // swizzled slot in pair P's 128B block; global src is a 64B row chunk.
    const int u    = lane & 7;
    const int rpar = u >> 2;              // which row of the pair
    const int uo   = u & 3;               // 16B offset within the row's 64B
    const char* gsrc[8];
    unsigned    sdst[8];
#pragma unroll
    for (int q = 0; q < 8; q++) {
        const int P    = warp * 32 + q * 4 + (lane >> 3);
        const int grow = min(p0 + 2 * P + rpar, NPATCH - 1);   // tail clamp
        gsrc[q] = (const char*)(patch + (size_t)grow * D) + uo * 16;
        sdst[q] = sb0 + (unsigned)(P * 128 + ((u ^ (P & 7)) * 16));
    }

#define ISSUE_STAGE(s, bufoff)                                                  \
    do {                                                                        \
        const int _go = (s) * (DC * 4);                                         \
        _Pragma("unroll")                                                       \
        for (int _q = 0; _q < 8; _q++) cp16(sdst[_q] + (bufoff), gsrc[_q] + _go); \
        asm volatile("cp.async.commit_group;" ::: "memory");                    \
    } while (0)

    // Kick DRAM with 3 stages before staging cues.
    ISSUE_STAGE(0, 0u);
    ISSUE_STAGE(1, (unsigned)STAGE_B);
    ISSUE_STAGE(2, (unsigned)(2 * STAGE_B));

    {   // cues = tokens[b, 0:5, :] (contiguous) -> smem
        const float4* cg = (const float4*)base;
        float4* cs = (float4*)cue_sm;
        for (int i = t; i < NCUE * D / 4; i += TPB) cs[i] = cg[i];
    }
    __syncthreads();

    // accumulators: 5 cues x 2 rows x 2 packed f32x2
    unsigned long long acc[NCUE][2][2];
#pragma unroll
    for (int c = 0; c < NCUE; c++)
#pragma unroll
        for (int r = 0; r < 2; r++) { acc[c][r][0] = 0ull; acc[c][r][1] = 0ull; }

    const unsigned pbase = sb0 + (unsigned)(t * 128);
    const int      swz   = t & 7;
    const unsigned cbase = (unsigned)__cvta_generic_to_shared(cue_sm);

    unsigned cons = 0;                            // byte offset of stage-s buffer
    for (int s = 0; s < NS; s++) {
        if (s < NS - 2)       asm volatile("cp.async.wait_group 2;" ::: "memory");
        else if (s == NS - 2) asm volatile("cp.async.wait_group 1;" ::: "memory");
        else                  asm volatile("cp.async.wait_group 0;" ::: "memory");
        __syncwarp();                             // lanes' copies of stage s visible

        const unsigned cb = cbase + (unsigned)(s * DC * 4);
#pragma unroll
        for (int j = 0; j < 4; j++) {
            unsigned long long aLo, aHi, bLo, bHi;
            lds_v2u64(aLo, aHi, pbase + cons + (unsigned)(((j      ^ swz) * 16)));
            lds_v2u64(bLo, bHi, pbase + cons + (unsigned)((((j + 4) ^ swz) * 16)));
#pragma unroll
            for (int c = 0; c < NCUE; c++) {
                unsigned long long qlo, qhi;
                lds_v2u64(qlo, qhi, cb + (unsigned)(c * D * 4 + j * 16));
                fma2(acc[c][0][0], aLo, qlo);
                fma2(acc[c][0][1], aHi, qhi);
                fma2(acc[c][1][0], bLo, qlo);
                fma2(acc[c][1][1], bHi, qhi);
            }
        }
        __syncwarp();                             // reads done before ring reuse
        if (s + 3 < NS) ISSUE_STAGE(s + 3, cons); // reuses the buffer just freed
        cons += (unsigned)STAGE_B;
        if (cons == (unsigned)(NBUF * STAGE_B)) cons = 0;
    }
#undef ISSUE_STAGE

    // finalize: 2 sims per cue -> packed keys -> warp/block/global max
    const int pA = min(p0 + 2 * t,     NPATCH - 1);
    const int pB = min(p0 + 2 * t + 1, NPATCH - 1);
    const unsigned lbA = 0xFFFFFFFFu - (unsigned)pA;
    const unsigned lbB = 0xFFFFFFFFu - (unsigned)pB;
    unsigned long long key[NCUE];
#pragma unroll
    for (int c = 0; c < NCUE; c++) {
        float sA = (__uint_as_float((unsigned)(acc[c][0][0] & 0xFFFFFFFFull)) +
                    __uint_as_float((unsigned)(acc[c][0][0] >> 32))) +
                   (__uint_as_float((unsigned)(acc[c][0][1] & 0xFFFFFFFFull)) +
                    __uint_as_float((unsigned)(acc[c][0][1] >> 32)));
        float sB = (__uint_as_float((unsigned)(acc[c][1][0] & 0xFFFFFFFFull)) +
                    __uint_as_float((unsigned)(acc[c][1][0] >> 32))) +
                   (__uint_as_float((unsigned)(acc[c][1][1] & 0xFFFFFFFFull)) +
                    __uint_as_float((unsigned)(acc[c][1][1] >> 32)));
        unsigned long long kA = ((unsigned long long)f2key(sA) << 32) | lbA;
        unsigned long long kB = ((unsigned long long)f2key(sB) << 32) | lbB;
        key[c] = (kA > kB) ? kA : kB;
    }
#pragma unroll
    for (int c = 0; c < NCUE; c++)
#pragma unroll
        for (int o = 16; o; o >>= 1) {
            unsigned long long other = __shfl_xor_sync(0xffffffffu, key[c], o);
            key[c] = (other > key[c]) ? other : key[c];
        }
    if (lane == 0)
#pragma unroll
        for (int c = 0; c < NCUE; c++) warp_best[warp][c] = key[c];
    __syncthreads();
    if (t < NCUE) {
        unsigned long long m = warp_best[0][t];
#pragma unroll
        for (int w = 1; w < TPB / 32; w++)
            m = (warp_best[w][t] > m) ? warp_best[w][t] : m;
        atomicMax(&g_best[b * NCUE + t], m);
    }
}

// ---------------------------------------------------------------------------
// Kernel 2 (proven, ~9us): build + normalize 10 output tokens per batch;
// fully unrolled masked 3x3 ROI; resets g_best for the next replay.
// ---------------------------------------------------------------------------
__global__ __launch_bounds__(256) void gather_kernel(const float* __restrict__ tokens,
                                                     float* __restrict__ out) {
    const int tk = blockIdx.x;
    const int b  = blockIdx.y;
    const float* base = tokens + (size_t)b * STOK * D;
    const int tid = threadIdx.x;

    float v[3];

    if (tk < NCUE) {
        const float* row = base + (size_t)tk * D;
#pragma unroll
        for (int j = 0; j < 3; j++) v[j] = row[tid + 256 * j];
    } else {
        const int c = tk - NCUE;
        const unsigned long long key = g_best[b * NCUE + c];
        const int idx = (int)(0xFFFFFFFFu - (unsigned)(key & 0xFFFFFFFFull));
        const int h = idx / G, w = idx % G;

        const float* prow[9];
        float        msk[9];
        float        cnt = 0.0f;
#pragma unroll
        for (int dr = -1; dr <= 1; dr++)
#pragma unroll
            for (int dc = -1; dc <= 1; dc++) {
                const int k  = (dr + 1) * 3 + (dc + 1);
                const int rr = h + dr, cc = w + dc;
                const bool ok = (rr >= 0) & (rr < G) & (cc >= 0) & (cc < G);
                const int rcl = min(max(rr, 0), G - 1);
                const int ccl = min(max(cc, 0), G - 1);
                prow[k] = base + (size_t)(NCUE + rcl * G + ccl) * D;
                msk[k]  = ok ? 1.0f : 0.0f;
                cnt += msk[k];
            }
        const float inv = 1.0f / cnt;
#pragma unroll
        for (int j = 0; j < 3; j++) v[j] = 0.0f;
#pragma unroll
        for (int k = 0; k < 9; k++) {
#pragma unroll
            for (int j = 0; j < 3; j++)
                v[j] = fmaf(msk[k], prow[k][tid + 256 * j], v[j]);
        }
#pragma unroll
        for (int j = 0; j < 3; j++) v[j] *= inv;
    }

    // block reduce sum of squares
    float ss = v[0] * v[0] + v[1] * v[1] + v[2] * v[2];
#pragma unroll
    for (int o = 16; o > 0; o >>= 1) ss += __shfl_xor_sync(0xffffffffu, ss, o);

    __shared__ float red[8];
    const int lane = tid & 31, warp = tid >> 5;
    if (lane == 0) red[warp] = ss;
    __syncthreads();   // also orders g_best reads before the reset below
    if (warp == 0) {
        float s2 = (lane < 8) ? red[lane] : 0.0f;
        s2 += __shfl_xor_sync(0xffffffffu, s2, 4);
        s2 += __shfl_xor_sync(0xffffffffu, s2, 2);
        s2 += __shfl_xor_sync(0xffffffffu, s2, 1);
        if (lane == 0) red[0] = s2;
    }
    // reset scratch for next replay (exactly one block owns each slot)
    if (tk >= NCUE && tid == 0) g_best[b * NCUE + (tk - NCUE)] = 0ull;
    __syncthreads();

    const float norm  = sqrtf(red[0]);
    const float scale = 1.0f / fmaxf(norm, EPSN);

    float* orow = out + ((size_t)b * 10 + tk) * D;
#pragma unroll
    for (int j = 0; j < 3; j++) orow[tid + 256 * j] = v[j] * scale;
}

extern "C" void kernel_launch(void* const* d_in, const int* in_sizes, int n_in,
                              void* d_out, int out_size) {
    const float* tokens = (const float*)d_in[0];
    float* out = (float*)d_out;

    cudaFuncSetAttribute(argmax_kernel,
                         cudaFuncAttributeMaxDynamicSharedMemorySize, DSM_B);

    argmax_kernel<<<dim3(NTILE, BATCH), TPB, DSM_B>>>(tokens);
    gather_kernel<<<dim3(10, BATCH), 256>>>(tokens, out);
}

// round 12
// speedup vs baseline: 1.1676x; 1.1676x over previous
#include <cuda_runtime.h>

#define G       37
#define NPATCH  (G * G)          // 1369
#define D       768
#define NCUE    5
#define STOK    (NCUE + NPATCH)  // 1374
#define BATCH   128
#define EPSN    1e-12f

#define TPB     128              // 1 patch per thread
#define PTILE   128
#define NTILE   11               // ceil(1369/128)
#define NITEMS  (NTILE * BATCH)  // 1408 work items
#define NBLK    592              // 4 blocks/SM x 148 SMs, persistent
#define DC      16               // dims per pipeline stage
#define NS      (D / DC)         // 48 stages
#define NBUF    4                // 4-deep ring, 3 stages in flight
#define F4ROW   (DC / 4)         // 4 float4 per row-stage
#define STAGE_F4 (PTILE * F4ROW) // 512 float4 = 8KB per buffer
#define STAGE_B  (STAGE_F4 * 16) // 8192

// packed argmax scratch: high 32 = orderable sim key, low 32 = ~idx (lowest idx
// wins ties). Zero-init at module load; gather_kernel resets after reading.
// Ticket/finished counters reset by the last persistent block to retire, so
// every graph replay starts from zeroed state (deterministic).
__device__ unsigned long long g_best[BATCH * NCUE];
__device__ unsigned           g_ticket;
__device__ unsigned           g_finished;

__device__ __forceinline__ unsigned f2key(float f) {
    unsigned u = __float_as_uint(f);
    return (u & 0x80000000u) ? ~u : (u | 0x80000000u);
}
__device__ __forceinline__ void fma2(unsigned long long& d, unsigned long long a,
                                     unsigned long long b) {
    asm volatile("fma.rn.f32x2 %0, %1, %2, %0;" : "+l"(d) : "l"(a), "l"(b));
}
__device__ __forceinline__ void lds_v2u64(unsigned long long& lo, unsigned long long& hi,
                                          unsigned addr) {
    asm volatile("ld.shared.v2.u64 {%0, %1}, [%2];" : "=l"(lo), "=l"(hi) : "r"(addr));
}
__device__ __forceinline__ void cp16(unsigned dst, const void* src) {
    asm volatile("cp.async.cg.shared.global [%0], [%1], 16;" :: "r"(dst), "l"(src)
                 : "memory");
}

// ---------------------------------------------------------------------------
// Kernel 1: persistent work-stealing argmax. R9's pipeline body (measured
// best: NBUF=4 ring, DC=16, wait_group-2 chain, warp-self-contained staging)
// wrapped in an atomic-ticket loop over 1408 (batch,tile) items. Removes the
// 2.38->3 tail-wave quantization that capped R9 at 73% DRAM.
// ---------------------------------------------------------------------------
__global__ __launch_bounds__(TPB, 4) void argmax_kernel(const float* __restrict__ tokens) {
    __shared__ float4 stage_buf[NBUF][STAGE_F4];        // 32 KB
    __shared__ float  cue_sm[NCUE * D];                 // 15 KB
    __shared__ unsigned long long warp_best[TPB / 32][NCUE];
    __shared__ unsigned sm_item;

    const int t    = threadIdx.x;
    const int lane = t & 31;
    const int warp = t >> 5;
    const unsigned sb0 = (unsigned)__cvta_generic_to_shared(&stage_buf[0][0]);

    // Item-invariant staging geometry: instr q (0..3) stages rows
    // R = 32w + 8q + (lane>>2), 16B segment lane&3 (contiguous 512B spans).
    const int seg = lane & 3;
    int     rrow[4];
    unsigned sdst[4];
#pragma unroll
    for (int q = 0; q < 4; q++) {
        const int R = warp * 32 + q * 8 + (lane >> 2);
        rrow[q] = R;
        sdst[q] = sb0 + (unsigned)(R * 64 + ((seg ^ ((R >> 1) & 3)) * 16));
    }
    const unsigned rbase = sb0 + (unsigned)(t * 64);
    const int      sw    = (t >> 1) & 3;
    const unsigned cbase = (unsigned)__cvta_generic_to_shared(cue_sm);

    for (;;) {
        if (t == 0) sm_item = atomicAdd(&g_ticket, 1u);
        __syncthreads();                         // also guards smem reuse
        const unsigned item = sm_item;
        if (item >= (unsigned)NITEMS) break;

        const int b  = (int)(item & (BATCH - 1));
        const int p0 = (int)(item >> 7) * PTILE;
        const float* base  = tokens + (size_t)b * STOK * D;
        const float* patch = base + NCUE * D;

        const char* gsrc[4];
#pragma unroll
        for (int q = 0; q < 4; q++) {
            const int pidx = min(p0 + rrow[q], NPATCH - 1);   // tail clamp
            gsrc[q] = (const char*)(patch + (size_t)pidx * D) + seg * 16;
        }

#define ISSUE_STAGE(s)                                                          \
    do {                                                                        \
        const unsigned _bo = (unsigned)(((s) & (NBUF - 1)) * STAGE_B);          \
        const int _go = (s) * (DC * 4);                                         \
        _Pragma("unroll")                                                       \
        for (int _q = 0; _q < 4; _q++) cp16(sdst[_q] + _bo, gsrc[_q] + _go);    \
        asm volatile("cp.async.commit_group;" ::: "memory");                    \
    } while (0)

        ISSUE_STAGE(0);
        ISSUE_STAGE(1);
        ISSUE_STAGE(2);

        {   // cues = tokens[b, 0:5, :] (contiguous; L2-resident across items)
            const float4* cg = (const float4*)base;
            float4* cs = (float4*)cue_sm;
            for (int i = t; i < NCUE * D / 4; i += TPB) cs[i] = cg[i];
        }
        __syncthreads();

        unsigned long long acc[NCUE][2];
#pragma unroll
        for (int c = 0; c < NCUE; c++) { acc[c][0] = 0ull; acc[c][1] = 0ull; }

        for (int s = 0; s < NS; s++) {
            if (s < NS - 2)       asm volatile("cp.async.wait_group 2;" ::: "memory");
            else if (s == NS - 2) asm volatile("cp.async.wait_group 1;" ::: "memory");
            else                  asm volatile("cp.async.wait_group 0;" ::: "memory");
            __syncwarp();                        // lanes' copies of stage s visible

            const unsigned bo = (unsigned)((s & (NBUF - 1)) * STAGE_B);
            const unsigned cb = cbase + (unsigned)(s * DC * 4);
#pragma unroll
            for (int j = 0; j < F4ROW; j++) {
                unsigned long long plo, phi;
                lds_v2u64(plo, phi, rbase + bo + (unsigned)(((j ^ sw) * 16)));
#pragma unroll
                for (int c = 0; c < NCUE; c++) {
                    unsigned long long qlo, qhi;
                    lds_v2u64(qlo, qhi, cb + (unsigned)(c * D * 4 + j * 16));
                    fma2(acc[c][0], plo, qlo);
                    fma2(acc[c][1], phi, qhi);
                }
            }
            __syncwarp();                        // reads done before ring reuse
            if (s + 3 < NS) ISSUE_STAGE(s + 3);
        }
#undef ISSUE_STAGE

        // finalize: per-thread sim -> packed key -> warp/block/global max
        const int pidx = min(p0 + t, NPATCH - 1);
        const unsigned lowbits = 0xFFFFFFFFu - (unsigned)pidx;
        unsigned long long key[NCUE];
#pragma unroll
        for (int c = 0; c < NCUE; c++) {
            float a0 = __uint_as_float((unsigned)(acc[c][0] & 0xFFFFFFFFull));
            float a1 = __uint_as_float((unsigned)(acc[c][0] >> 32));
            float a2 = __uint_as_float((unsigned)(acc[c][1] & 0xFFFFFFFFull));
            float a3 = __uint_as_float((unsigned)(acc[c][1] >> 32));
            float sim = (a0 + a1) + (a2 + a3);
            key[c] = ((unsigned long long)f2key(sim) << 32) | lowbits;
        }
#pragma unroll
        for (int c = 0; c < NCUE; c++)
#pragma unroll
            for (int o = 16; o; o >>= 1) {
                unsigned long long other = __shfl_xor_sync(0xffffffffu, key[c], o);
                key[c] = (other > key[c]) ? other : key[c];
            }
        if (lane == 0)
#pragma unroll
            for (int c = 0; c < NCUE; c++) warp_best[warp][c] = key[c];
        __syncthreads();
        if (t < NCUE) {
            unsigned long long m = warp_best[0][t];
#pragma unroll
            for (int w = 1; w < TPB / 32; w++)
                m = (warp_best[w][t] > m) ? warp_best[w][t] : m;
            atomicMax(&g_best[b * NCUE + t], m);
        }
    }

    // retire: last block resets the counters for the next graph replay
    if (t == 0) {
        __threadfence();
        const unsigned prev = atomicAdd(&g_finished, 1u);
        if (prev == (unsigned)(NBLK - 1)) {
            g_ticket   = 0u;
            g_finished = 0u;
        }
    }
}

// ---------------------------------------------------------------------------
// Kernel 2 (proven, ~9us): build + normalize 10 output tokens per batch;
// fully unrolled masked 3x3 ROI; resets g_best for the next replay.
// ---------------------------------------------------------------------------
__global__ __launch_bounds__(256) void gather_kernel(const float* __restrict__ tokens,
                                                     float* __restrict__ out) {
    const int tk = blockIdx.x;
    const int b  = blockIdx.y;
    const float* base = tokens + (size_t)b * STOK * D;
    const int tid = threadIdx.x;

    float v[3];

    if (tk < NCUE) {
        const float* row = base + (size_t)tk * D;
#pragma unroll
        for (int j = 0; j < 3; j++) v[j] = row[tid + 256 * j];
    } else {
        const int c = tk - NCUE;
        const unsigned long long key = g_best[b * NCUE + c];
        const int idx = (int)(0xFFFFFFFFu - (unsigned)(key & 0xFFFFFFFFull));
        const int h = idx / G, w = idx % G;

        const float* prow[9];
        float        msk[9];
        float        cnt = 0.0f;
#pragma unroll
        for (int dr = -1; dr <= 1; dr++)
#pragma unroll
            for (int dc = -1; dc <= 1; dc++) {
                const int k  = (dr + 1) * 3 + (dc + 1);
                const int rr = h + dr, cc = w + dc;
                const bool ok = (rr >= 0) & (rr < G) & (cc >= 0) & (cc < G);
                const int rcl = min(max(rr, 0), G - 1);
                const int ccl = min(max(cc, 0), G - 1);
                prow[k] = base + (size_t)(NCUE + rcl * G + ccl) * D;
                msk[k]  = ok ? 1.0f : 0.0f;
                cnt += msk[k];
            }
        const float inv = 1.0f / cnt;
#pragma unroll
        for (int j = 0; j < 3; j++) v[j] = 0.0f;
#pragma unroll
        for (int k = 0; k < 9; k++) {
#pragma unroll
            for (int j = 0; j < 3; j++)
                v[j] = fmaf(msk[k], prow[k][tid + 256 * j], v[j]);
        }
#pragma unroll
        for (int j = 0; j < 3; j++) v[j] *= inv;
    }

    // block reduce sum of squares
    float ss = v[0] * v[0] + v[1] * v[1] + v[2] * v[2];
#pragma unroll
    for (int o = 16; o > 0; o >>= 1) ss += __shfl_xor_sync(0xffffffffu, ss, o);

    __shared__ float red[8];
    const int lane = tid & 31, warp = tid >> 5;
    if (lane == 0) red[warp] = ss;
    __syncthreads();   // also orders g_best reads before the reset below
    if (warp == 0) {
        float s2 = (lane < 8) ? red[lane] : 0.0f;
        s2 += __shfl_xor_sync(0xffffffffu, s2, 4);
        s2 += __shfl_xor_sync(0xffffffffu, s2, 2);
        s2 += __shfl_xor_sync(0xffffffffu, s2, 1);
        if (lane == 0) red[0] = s2;
    }
    // reset scratch for next replay (exactly one block owns each slot)
    if (tk >= NCUE && tid == 0) g_best[b * NCUE + (tk - NCUE)] = 0ull;
    __syncthreads();

    const float norm  = sqrtf(red[0]);
    const float scale = 1.0f / fmaxf(norm, EPSN);

    float* orow = out + ((size_t)b * 10 + tk) * D;
#pragma unroll
    for (int j = 0; j < 3; j++) orow[tid + 256 * j] = v[j] * scale;
}

extern "C" void kernel_launch(void* const* d_in, const int* in_sizes, int n_in,
                              void* d_out, int out_size) {
    const float* tokens = (const float*)d_in[0];
    float* out = (float*)d_out;

    argmax_kernel<<<NBLK, TPB>>>(tokens);
    gather_kernel<<<dim3(10, BATCH), 256>>>(tokens, out);
}

// round 13
// speedup vs baseline: 1.2063x; 1.0331x over previous
#include <cuda_runtime.h>

#define G       37
#define NPATCH  (G * G)          // 1369
#define D       768
#define NCUE    5
#define STOK    (NCUE + NPATCH)  // 1374
#define BATCH   128
#define EPSN    1e-12f

#define TPB     128              // 1 patch per thread
#define PTILE   128
#define NTILE   11               // ceil(1369/128)
#define N_AM    (NTILE * BATCH)  // 1408 argmax items
#define N_ROI   (BATCH * NCUE)   // 640 ROI-token items
#define NITEMS_ALL (N_AM + N_ROI)
#define NBLK    592              // 4 blocks/SM x 148 SMs, persistent
#define DC      16               // dims per pipeline stage
#define NS      (D / DC)         // 48 stages
#define NBUF    4                // 4-deep ring, 3 stages in flight
#define F4ROW   (DC / 4)         // 4 float4 per row-stage
#define STAGE_F4 (PTILE * F4ROW) // 512 float4 = 8KB per buffer
#define STAGE_B  (STAGE_F4 * 16) // 8192

// Cross-item scratch. All reset in-kernel (ROI items reset their g_best slot;
// the last retiring block resets g_done/ticket/finished) so every graph
// replay starts from zeroed state (deterministic).
__device__ unsigned long long g_best[BATCH * NCUE];
__device__ unsigned           g_done[BATCH];
__device__ unsigned           g_ticket;
__device__ unsigned           g_finished;

__device__ __forceinline__ unsigned f2key(float f) {
    unsigned u = __float_as_uint(f);
    return (u & 0x80000000u) ? ~u : (u | 0x80000000u);
}
__device__ __forceinline__ void fma2(unsigned long long& d, unsigned long long a,
                                     unsigned long long b) {
    asm volatile("fma.rn.f32x2 %0, %1, %2, %0;" : "+l"(d) : "l"(a), "l"(b));
}
__device__ __forceinline__ void lds_v2u64(unsigned long long& lo, unsigned long long& hi,
                                          unsigned addr) {
    asm volatile("ld.shared.v2.u64 {%0, %1}, [%2];" : "=l"(lo), "=l"(hi) : "r"(addr));
}
__device__ __forceinline__ void cp16(unsigned dst, const void* src) {
    asm volatile("cp.async.cg.shared.global [%0], [%1], 16;" :: "r"(dst), "l"(src)
                 : "memory");
}

// ---------------------------------------------------------------------------
// Single persistent kernel. Ticket space: [0,1408) argmax tiles
// (batch-consecutive), [1408,2048) ROI-token gather items (batch-ordered,
// spin on g_done[b]==11). Cue-token outputs are written by each batch's
// tile-0 block directly from its smem-resident cues. Gather work overlaps
// the argmax drain instead of running serially after it.
// ---------------------------------------------------------------------------
__global__ __launch_bounds__(TPB, 4) void fused_kernel(const float* __restrict__ tokens,
                                                       float* __restrict__ out) {
    __shared__ float4 stage_buf[NBUF][STAGE_F4];        // 32 KB
    __shared__ float  cue_sm[NCUE * D];                 // 15 KB
    __shared__ unsigned long long warp_best[TPB / 32][NCUE];
    __shared__ unsigned sm_item;
    __shared__ int      sm_idx;
    __shared__ float    red4[4];

    const int t    = threadIdx.x;
    const int lane = t & 31;
    const int warp = t >> 5;
    const unsigned sb0 = (unsigned)__cvta_generic_to_shared(&stage_buf[0][0]);

    // Item-invariant staging geometry: instr q (0..3) stages rows
    // R = 32w + 8q + (lane>>2), 16B segment lane&3 (contiguous 512B spans).
    const int seg = lane & 3;
    int      rrow[4];
    unsigned sdst[4];
#pragma unroll
    for (int q = 0; q < 4; q++) {
        const int R = warp * 32 + q * 8 + (lane >> 2);
        rrow[q] = R;
        sdst[q] = sb0 + (unsigned)(R * 64 + ((seg ^ ((R >> 1) & 3)) * 16));
    }
    const unsigned rbase = sb0 + (unsigned)(t * 64);
    const int      sw    = (t >> 1) & 3;
    const unsigned cbase = (unsigned)__cvta_generic_to_shared(cue_sm);

    for (;;) {
        if (t == 0) sm_item = atomicAdd(&g_ticket, 1u);
        __syncthreads();                         // also guards smem reuse
        const unsigned item = sm_item;
        if (item >= (unsigned)NITEMS_ALL) break;

        if (item < (unsigned)N_AM) {
            // ================= argmax tile item =================
            const int b    = (int)(item / NTILE);
            const int tile = (int)(item - (unsigned)(b * NTILE));
            const int p0   = tile * PTILE;
            const float* base  = tokens + (size_t)b * STOK * D;
            const float* patch = base + NCUE * D;

            const char* gsrc[4];
#pragma unroll
            for (int q = 0; q < 4; q++) {
                const int pidx = min(p0 + rrow[q], NPATCH - 1);   // tail clamp
                gsrc[q] = (const char*)(patch + (size_t)pidx * D) + seg * 16;
            }

#define ISSUE_STAGE(s)                                                          \
    do {                                                                        \
        const unsigned _bo = (unsigned)(((s) & (NBUF - 1)) * STAGE_B);          \
        const int _go = (s) * (DC * 4);                                         \
        _Pragma("unroll")                                                       \
        for (int _q = 0; _q < 4; _q++) cp16(sdst[_q] + _bo, gsrc[_q] + _go);    \
        asm volatile("cp.async.commit_group;" ::: "memory");                    \
    } while (0)

            ISSUE_STAGE(0);
            ISSUE_STAGE(1);
            ISSUE_STAGE(2);

            {   // cues = tokens[b, 0:5, :] (contiguous; L2-resident)
                const float4* cg = (const float4*)base;
                float4* cs = (float4*)cue_sm;
                for (int i = t; i < NCUE * D / 4; i += TPB) cs[i] = cg[i];
            }
            __syncthreads();

            unsigned long long acc[NCUE][2];
#pragma unroll
            for (int c = 0; c < NCUE; c++) { acc[c][0] = 0ull; acc[c][1] = 0ull; }

            for (int s = 0; s < NS; s++) {
                if (s < NS - 2)       asm volatile("cp.async.wait_group 2;" ::: "memory");
                else if (s == NS - 2) asm volatile("cp.async.wait_group 1;" ::: "memory");
                else                  asm volatile("cp.async.wait_group 0;" ::: "memory");
                __syncwarp();

                const unsigned bo = (unsigned)((s & (NBUF - 1)) * STAGE_B);
                const unsigned cb = cbase + (unsigned)(s * DC * 4);
#pragma unroll
                for (int j = 0; j < F4ROW; j++) {
                    unsigned long long plo, phi;
                    lds_v2u64(plo, phi, rbase + bo + (unsigned)(((j ^ sw) * 16)));
#pragma unroll
                    for (int c = 0; c < NCUE; c++) {
                        unsigned long long qlo, qhi;
                        lds_v2u64(qlo, qhi, cb + (unsigned)(c * D * 4 + j * 16));
                        fma2(acc[c][0], plo, qlo);
                        fma2(acc[c][1], phi, qhi);
                    }
                }
                __syncwarp();
                if (s + 3 < NS) ISSUE_STAGE(s + 3);
            }
#undef ISSUE_STAGE

            const int pidx = min(p0 + t, NPATCH - 1);
            const unsigned lowbits = 0xFFFFFFFFu - (unsigned)pidx;
            unsigned long long key[NCUE];
#pragma unroll
            for (int c = 0; c < NCUE; c++) {
                float a0 = __uint_as_float((unsigned)(acc[c][0] & 0xFFFFFFFFull));
                float a1 = __uint_as_float((unsigned)(acc[c][0] >> 32));
                float a2 = __uint_as_float((unsigned)(acc[c][1] & 0xFFFFFFFFull));
                float a3 = __uint_as_float((unsigned)(acc[c][1] >> 32));
                float sim = (a0 + a1) + (a2 + a3);
                key[c] = ((unsigned long long)f2key(sim) << 32) | lowbits;
            }
#pragma unroll
            for (int c = 0; c < NCUE; c++)
#pragma unroll
                for (int o = 16; o; o >>= 1) {
                    unsigned long long other = __shfl_xor_sync(0xffffffffu, key[c], o);
                    key[c] = (other > key[c]) ? other : key[c];
                }
            if (lane == 0)
#pragma unroll
                for (int c = 0; c < NCUE; c++) warp_best[warp][c] = key[c];
            __syncthreads();
            if (t < NCUE) {
                unsigned long long m = warp_best[0][t];
#pragma unroll
                for (int w = 1; w < TPB / 32; w++)
                    m = (warp_best[w][t] > m) ? warp_best[w][t] : m;
                atomicMax(&g_best[b * NCUE + t], m);
                __threadfence();                 // publish before g_done bump
            }
            __syncthreads();
            if (t == 0) atomicAdd(&g_done[b], 1u);

            // tile-0 block also emits the 5 cue-token outputs from cue_sm
            // (independent of argmax results; hidden under remaining work)
            if (tile == 0) {
#pragma unroll 1
                for (int tk = 0; tk < NCUE; tk++) {
                    float v[6];
#pragma unroll
                    for (int j = 0; j < 6; j++) v[j] = cue_sm[tk * D + t + 128 * j];
                    float ss = 0.0f;
#pragma unroll
                    for (int j = 0; j < 6; j++) ss += v[j] * v[j];
#pragma unroll
                    for (int o = 16; o > 0; o >>= 1)
                        ss += __shfl_xor_sync(0xffffffffu, ss, o);
                    if (lane == 0) red4[warp] = ss;
                    __syncthreads();
                    float tot = red4[0] + red4[1] + red4[2] + red4[3];
                    __syncthreads();
                    const float scale = 1.0f / fmaxf(sqrtf(tot), EPSN);
                    float* orow = out + ((size_t)b * 10 + tk) * D;
#pragma unroll
                    for (int j = 0; j < 6; j++) orow[t + 128 * j] = v[j] * scale;
                }
            }
        } else {
            // ================= ROI-token gather item =================
            const unsigned gid = item - (unsigned)N_AM;
            const int b = (int)(gid / NCUE);
            const int c = (int)(gid - (unsigned)(b * NCUE));

            if (t == 0) {
                unsigned d;
                do {
                    asm volatile("ld.acquire.gpu.u32 %0, [%1];"
                                 : "=r"(d) : "l"(&g_done[b]) : "memory");
                    if (d < (unsigned)NTILE) __nanosleep(200);
                } while (d < (unsigned)NTILE);
                const unsigned long long key = atomicAdd(&g_best[b * NCUE + c], 0ull);
                sm_idx = (int)(0xFFFFFFFFu - (unsigned)(key & 0xFFFFFFFFull));
                g_best[b * NCUE + c] = 0ull;     // reset for next replay
            }
            __syncthreads();

            const int idx = sm_idx;
            const int h = idx / G, w = idx % G;
            const float* patch = tokens + (size_t)b * STOK * D + NCUE * D;

            const float* prow[9];
            float msk[9];
            float cnt = 0.0f;
#pragma unroll
            for (int dr = -1; dr <= 1; dr++)
#pragma unroll
                for (int dc2 = -1; dc2 <= 1; dc2++) {
                    const int k  = (dr + 1) * 3 + (dc2 + 1);
                    const int rr = h + dr, cc = w + dc2;
                    const bool ok = (rr >= 0) & (rr < G) & (cc >= 0) & (cc < G);
                    const int rcl = min(max(rr, 0), G - 1);
                    const int ccl = min(max(cc, 0), G - 1);
                    prow[k] = patch + (size_t)(rcl * G + ccl) * D;
                    msk[k]  = ok ? 1.0f : 0.0f;
                    cnt += msk[k];
                }
            const float inv = 1.0f / cnt;

            float v[6];
#pragma unroll
            for (int j = 0; j < 6; j++) v[j] = 0.0f;
#pragma unroll
            for (int k = 0; k < 9; k++)
#pragma unroll
                for (int j = 0; j < 6; j++)
                    v[j] = fmaf(msk[k], prow[k][t + 128 * j], v[j]);
#pragma unroll
            for (int j = 0; j < 6; j++) v[j] *= inv;

            float ss = 0.0f;
#pragma unroll
            for (int j = 0; j < 6; j++) ss += v[j] * v[j];
#pragma unroll
            for (int o = 16; o > 0; o >>= 1) ss += __shfl_xor_sync(0xffffffffu, ss, o);
            if (lane == 0) red4[warp] = ss;
            __syncthreads();
            const float tot = red4[0] + red4[1] + red4[2] + red4[3];
            __syncthreads();
            const float scale = 1.0f / fmaxf(sqrtf(tot), EPSN);

            float* orow = out + ((size_t)b * 10 + NCUE + c) * D;
#pragma unroll
            for (int j = 0; j < 6; j++) orow[t + 128 * j] = v[j] * scale;
        }
    }

    // retire: last block resets counters for the next graph replay
    if (t == 0) {
        __threadfence();
        const unsigned prev = atomicAdd(&g_finished, 1u);
        if (prev == (unsigned)(NBLK - 1)) {
            for (int i = 0; i < BATCH; i++) g_done[i] = 0u;
            g_ticket   = 0u;
            g_finished = 0u;
        }
    }
}

extern "C" void kernel_launch(void* const* d_in, const int* in_sizes, int n_in,
                              void* d_out, int out_size) {
    const float* tokens = (const float*)d_in[0];
    float* out = (float*)d_out;

    fused_kernel<<<NBLK, TPB>>>(tokens, out);
}